// round 4
// baseline (speedup 1.0000x reference)
#include <cuda_runtime.h>

// Fused SegmentationAugmentation, row-hoisted, occupancy-tuned:
//   out[0 .. 2^24)     = trilinear(border) affine sample of input_g   (float)
//   out[2^24 .. 2^25)  = (same sample of label_g) > 0.5               (1.0f/0.0f)
//
// One warp per output (b,d,h) row of 128 voxels; lane handles w = lane + 32k.
// T = t @ rot(z) has T[0,2] = T[1,2] = 0, so the x/y sampling pipeline is
// row-constant and hoisted (warp-uniform fast path + exact generic fallback).
// All FP ops use __f*_rn to replicate reference rounding bit-exactly.
// __launch_bounds__(256, 6) caps regs (~42) to keep 48 warps/SM resident.

#define N_VOX (1 << 24)   // 8 * 128^3

__device__ __forceinline__ float unnorm_clamp(float c)
{
    // clip(((c+1)*128 - 1)*0.5, 0, 127) with reference rounding sequence
    return fminf(fmaxf(__fmul_rn(__fsub_rn(__fmul_rn(__fadd_rn(c, 1.0f), 128.0f), 1.0f), 0.5f),
                       0.0f), 127.0f);
}

__global__ __launch_bounds__(256, 6)
void seg_aug_kernel(const float* __restrict__ inp,
                    const float* __restrict__ lab,
                    const float* __restrict__ T,
                    float* __restrict__ out)
{
    const int lane = threadIdx.x & 31;
    const int row  = blockIdx.x * 8 + (threadIdx.x >> 5);  // 131072 rows total

    const int h = row & 127;
    const int d = (row >> 7) & 127;
    const int b = row >> 14;

    const float inv128 = 1.0f / 128.0f;
    const float xn = (2.0f * (float)d + 1.0f) * inv128 - 1.0f;
    const float yn = (2.0f * (float)h + 1.0f) * inv128 - 1.0f;

    const float t00 = __ldg(T + 0), t01 = __ldg(T + 1), t02 = __ldg(T + 2),  t03 = __ldg(T + 3);
    const float t10 = __ldg(T + 4), t11 = __ldg(T + 5), t12 = __ldg(T + 6),  t13 = __ldg(T + 7);
    const float t20 = __ldg(T + 8), t21 = __ldg(T + 9), t22 = __ldg(T + 10), t23 = __ldg(T + 11);

    // exact reference prefixes (t0*xn + t1*yn), constant along the row
    const float ux = __fadd_rn(__fmul_rn(t00, xn), __fmul_rn(t01, yn));
    const float uy = __fadd_rn(__fmul_rn(t10, xn), __fmul_rn(t11, yn));
    const float uz = __fadd_rn(__fmul_rn(t20, xn), __fmul_rn(t21, yn));

    const int out_base = row << 7;
    const int vol_base = b << 21;

    const bool fastxy = (t02 == 0.0f) && (t12 == 0.0f);   // warp-uniform

    if (fastxy) {
        // x/y pipeline hoisted (bit-exact: adding t02*zn = +/-0 can't change
        // the clamped coordinate)
        const float X = unnorm_clamp(__fadd_rn(ux, t03));
        const float Y = unnorm_clamp(__fadd_rn(uy, t13));
        const float x0f = floorf(X), y0f = floorf(Y);
        const float fx = __fsub_rn(X, x0f);
        const float fy = __fsub_rn(Y, y0f);
        const int x0 = (int)x0f, y0 = (int)y0f;
        const int x1 = min(x0 + 1, 127);
        const int y1 = min(y0 + 1, 127);
        const float wx0 = __fsub_rn(1.0f, fx), wx1 = fx;
        const float wy0 = __fsub_rn(1.0f, fy), wy1 = fy;

        // 4 integer row offsets shared by inp and lab (halves address regs)
        const int r00 = vol_base + (x0 << 14) + (y0 << 7);
        const int r01 = vol_base + (x0 << 14) + (y1 << 7);
        const int r10 = vol_base + (x1 << 14) + (y0 << 7);
        const int r11 = vol_base + (x1 << 14) + (y1 << 7);

        #pragma unroll
        for (int k = 0; k < 4; k++) {
            const int w = lane + 32 * k;
            const float zn = (2.0f * (float)w + 1.0f) * inv128 - 1.0f;
            const float zs = __fadd_rn(__fadd_rn(uz, __fmul_rn(t22, zn)), t23);
            const float Z = unnorm_clamp(zs);
            const float z0f = floorf(Z);
            const float fz = __fsub_rn(Z, z0f);
            const int z0 = (int)z0f;
            const int z1 = min(z0 + 1, 127);
            const float wz0 = __fsub_rn(1.0f, fz), wz1 = fz;

            const float m00 = __fmul_rn(wz0, wy0);
            const float m01 = __fmul_rn(wz0, wy1);
            const float m10 = __fmul_rn(wz1, wy0);
            const float m11 = __fmul_rn(wz1, wy1);
            const float wA = __fmul_rn(m00, wx0), wB = __fmul_rn(m00, wx1);
            const float wC = __fmul_rn(m01, wx0), wD = __fmul_rn(m01, wx1);
            const float wE = __fmul_rn(m10, wx0), wF = __fmul_rn(m10, wx1);
            const float wG = __fmul_rn(m11, wx0), wH = __fmul_rn(m11, wx1);

            // issue all 16 gathers up front (independent), then two exact
            // left-assoc accumulation chains, interleaved for ILP
            const float iA = __ldg(inp + r00 + z0), lA = __ldg(lab + r00 + z0);
            const float iB = __ldg(inp + r10 + z0), lB = __ldg(lab + r10 + z0);
            const float iC = __ldg(inp + r01 + z0), lC = __ldg(lab + r01 + z0);
            const float iD = __ldg(inp + r11 + z0), lD = __ldg(lab + r11 + z0);
            const float iE = __ldg(inp + r00 + z1), lE = __ldg(lab + r00 + z1);
            const float iF = __ldg(inp + r10 + z1), lF = __ldg(lab + r10 + z1);
            const float iG = __ldg(inp + r01 + z1), lG = __ldg(lab + r01 + z1);
            const float iH = __ldg(inp + r11 + z1), lH = __ldg(lab + r11 + z1);

            float ai = 0.0f, al = 0.0f;
            ai = __fadd_rn(ai, __fmul_rn(iA, wA));  al = __fadd_rn(al, __fmul_rn(lA, wA));
            ai = __fadd_rn(ai, __fmul_rn(iB, wB));  al = __fadd_rn(al, __fmul_rn(lB, wB));
            ai = __fadd_rn(ai, __fmul_rn(iC, wC));  al = __fadd_rn(al, __fmul_rn(lC, wC));
            ai = __fadd_rn(ai, __fmul_rn(iD, wD));  al = __fadd_rn(al, __fmul_rn(lD, wD));
            ai = __fadd_rn(ai, __fmul_rn(iE, wE));  al = __fadd_rn(al, __fmul_rn(lE, wE));
            ai = __fadd_rn(ai, __fmul_rn(iF, wF));  al = __fadd_rn(al, __fmul_rn(lF, wF));
            ai = __fadd_rn(ai, __fmul_rn(iG, wG));  al = __fadd_rn(al, __fmul_rn(lG, wG));
            ai = __fadd_rn(ai, __fmul_rn(iH, wH));  al = __fadd_rn(al, __fmul_rn(lH, wH));

            out[out_base + w] = ai;
            out[out_base + w + N_VOX] = (al > 0.5f) ? 1.0f : 0.0f;
        }
    } else {
        // generic exact path: per-voxel full coordinate pipeline
        #pragma unroll 2
        for (int k = 0; k < 4; k++) {
            const int w = lane + 32 * k;
            const float zn = (2.0f * (float)w + 1.0f) * inv128 - 1.0f;
            const float xs = __fadd_rn(__fadd_rn(ux, __fmul_rn(t02, zn)), t03);
            const float ys = __fadd_rn(__fadd_rn(uy, __fmul_rn(t12, zn)), t13);
            const float zs = __fadd_rn(__fadd_rn(uz, __fmul_rn(t22, zn)), t23);
            const float X = unnorm_clamp(xs);
            const float Y = unnorm_clamp(ys);
            const float Z = unnorm_clamp(zs);
            const float x0f = floorf(X), y0f = floorf(Y), z0f = floorf(Z);
            const float fx = __fsub_rn(X, x0f);
            const float fy = __fsub_rn(Y, y0f);
            const float fz = __fsub_rn(Z, z0f);
            const int x0 = (int)x0f, y0 = (int)y0f, z0 = (int)z0f;
            const int x1 = min(x0 + 1, 127);
            const int y1 = min(y0 + 1, 127);
            const int z1 = min(z0 + 1, 127);
            const float wx0 = __fsub_rn(1.0f, fx), wx1 = fx;
            const float wy0 = __fsub_rn(1.0f, fy), wy1 = fy;
            const float wz0 = __fsub_rn(1.0f, fz), wz1 = fz;

            const int r00 = vol_base + (x0 << 14) + (y0 << 7);
            const int r01 = vol_base + (x0 << 14) + (y1 << 7);
            const int r10 = vol_base + (x1 << 14) + (y0 << 7);
            const int r11 = vol_base + (x1 << 14) + (y1 << 7);

            const float m00 = __fmul_rn(wz0, wy0);
            const float m01 = __fmul_rn(wz0, wy1);
            const float m10 = __fmul_rn(wz1, wy0);
            const float m11 = __fmul_rn(wz1, wy1);
            const float wA = __fmul_rn(m00, wx0), wB = __fmul_rn(m00, wx1);
            const float wC = __fmul_rn(m01, wx0), wD = __fmul_rn(m01, wx1);
            const float wE = __fmul_rn(m10, wx0), wF = __fmul_rn(m10, wx1);
            const float wG = __fmul_rn(m11, wx0), wH = __fmul_rn(m11, wx1);

            float ai = 0.0f, al = 0.0f;
            ai = __fadd_rn(ai, __fmul_rn(__ldg(inp + r00 + z0), wA));
            al = __fadd_rn(al, __fmul_rn(__ldg(lab + r00 + z0), wA));
            ai = __fadd_rn(ai, __fmul_rn(__ldg(inp + r10 + z0), wB));
            al = __fadd_rn(al, __fmul_rn(__ldg(lab + r10 + z0), wB));
            ai = __fadd_rn(ai, __fmul_rn(__ldg(inp + r01 + z0), wC));
            al = __fadd_rn(al, __fmul_rn(__ldg(lab + r01 + z0), wC));
            ai = __fadd_rn(ai, __fmul_rn(__ldg(inp + r11 + z0), wD));
            al = __fadd_rn(al, __fmul_rn(__ldg(lab + r11 + z0), wD));
            ai = __fadd_rn(ai, __fmul_rn(__ldg(inp + r00 + z1), wE));
            al = __fadd_rn(al, __fmul_rn(__ldg(lab + r00 + z1), wE));
            ai = __fadd_rn(ai, __fmul_rn(__ldg(inp + r10 + z1), wF));
            al = __fadd_rn(al, __fmul_rn(__ldg(lab + r10 + z1), wF));
            ai = __fadd_rn(ai, __fmul_rn(__ldg(inp + r01 + z1), wG));
            al = __fadd_rn(al, __fmul_rn(__ldg(lab + r01 + z1), wG));
            ai = __fadd_rn(ai, __fmul_rn(__ldg(inp + r11 + z1), wH));
            al = __fadd_rn(al, __fmul_rn(__ldg(lab + r11 + z1), wH));

            out[out_base + w] = ai;
            out[out_base + w + N_VOX] = (al > 0.5f) ? 1.0f : 0.0f;
        }
    }
}

extern "C" void kernel_launch(void* const* d_in, const int* in_sizes, int n_in,
                              void* d_out, int out_size)
{
    const float* inp = (const float*)d_in[0];   // input_g  [8,1,128,128,128]
    const float* lab = (const float*)d_in[1];   // label_g  [8,1,128,128,128]
    const float* T   = (const float*)d_in[2];   // transform 4x4 (16 floats)
    float* out = (float*)d_out;

    // 131072 rows, 8 rows (warps) per block
    seg_aug_kernel<<<16384, 256>>>(inp, lab, T, out);
}

// round 5
// speedup vs baseline: 1.1865x; 1.1865x over previous
#include <cuda_runtime.h>

// Fused SegmentationAugmentation, row-hoisted, split-phase:
//   out[0 .. 2^24)     = trilinear(border) affine sample of input_g   (float)
//   out[2^24 .. 2^25)  = (same sample of label_g) > 0.5               (1.0f/0.0f)
//
// One warp per output (b,d,h) row; lane handles w = lane + 32k, k=0..3.
// T = t @ rot(z) => T[0,2] = T[1,2] = 0, so x/y sampling pipeline is
// row-constant (warp-uniform fast path; exact generic fallback).
// Label chain keeps the exact reference rounding sequence (__f*_rn,
// left-assoc); input chain may use FMA (tolerance 1e-3, measured 7.5e-6).

#define N_VOX (1 << 24)   // 8 * 128^3

__device__ __forceinline__ float unnorm_clamp(float c)
{
    // clip(((c+1)*128 - 1)*0.5, 0, 127) with reference rounding sequence
    return fminf(fmaxf(__fmul_rn(__fsub_rn(__fmul_rn(__fadd_rn(c, 1.0f), 128.0f), 1.0f), 0.5f),
                       0.0f), 127.0f);
}

__global__ __launch_bounds__(256, 5)
void seg_aug_kernel(const float* __restrict__ inp,
                    const float* __restrict__ lab,
                    const float* __restrict__ T,
                    float* __restrict__ out)
{
    const int lane = threadIdx.x & 31;
    const int row  = blockIdx.x * 8 + (threadIdx.x >> 5);  // 131072 rows

    const int h = row & 127;
    const int d = (row >> 7) & 127;
    const int b = row >> 14;

    const float inv128 = 1.0f / 128.0f;
    const float xn = (2.0f * (float)d + 1.0f) * inv128 - 1.0f;
    const float yn = (2.0f * (float)h + 1.0f) * inv128 - 1.0f;
    // zn for this lane at k=0; zn(k) = zn0 + 0.5k is bit-exact (multiples of
    // 1/128, |value| < 1, fits in 24-bit mantissa exactly)
    const float zn0 = (2.0f * (float)lane + 1.0f) * inv128 - 1.0f;

    const float t00 = __ldg(T + 0), t01 = __ldg(T + 1), t02 = __ldg(T + 2),  t03 = __ldg(T + 3);
    const float t10 = __ldg(T + 4), t11 = __ldg(T + 5), t12 = __ldg(T + 6),  t13 = __ldg(T + 7);
    const float t20 = __ldg(T + 8), t21 = __ldg(T + 9), t22 = __ldg(T + 10), t23 = __ldg(T + 11);

    // exact reference prefixes (t0*xn + t1*yn), row-constant
    const float ux = __fadd_rn(__fmul_rn(t00, xn), __fmul_rn(t01, yn));
    const float uy = __fadd_rn(__fmul_rn(t10, xn), __fmul_rn(t11, yn));
    const float uz = __fadd_rn(__fmul_rn(t20, xn), __fmul_rn(t21, yn));

    const int out_base = row << 7;
    const int vol_base = b << 21;

    const bool fastxy = (t02 == 0.0f) && (t12 == 0.0f);   // warp-uniform

    if (fastxy) {
        // hoisted x/y pipeline (bit-exact: adding t02*zn = +/-0 can't change
        // the clamped coordinate)
        const float X = unnorm_clamp(__fadd_rn(ux, t03));
        const float Y = unnorm_clamp(__fadd_rn(uy, t13));
        const float x0f = floorf(X), y0f = floorf(Y);
        const float fx = __fsub_rn(X, x0f);
        const float fy = __fsub_rn(Y, y0f);
        const int x0 = (int)x0f, y0 = (int)y0f;
        const int x1 = min(x0 + 1, 127);
        const int y1 = min(y0 + 1, 127);
        const float wx0 = __fsub_rn(1.0f, fx), wx1 = fx;
        const float wy0 = __fsub_rn(1.0f, fy), wy1 = fy;

        // cached row pointers (keeps per-load address math to one IADD)
        const float* pi00 = inp + vol_base + (x0 << 14) + (y0 << 7);
        const float* pi01 = inp + vol_base + (x0 << 14) + (y1 << 7);
        const float* pi10 = inp + vol_base + (x1 << 14) + (y0 << 7);
        const float* pi11 = inp + vol_base + (x1 << 14) + (y1 << 7);
        const float* pl00 = lab + vol_base + (x0 << 14) + (y0 << 7);
        const float* pl01 = lab + vol_base + (x0 << 14) + (y1 << 7);
        const float* pl10 = lab + vol_base + (x1 << 14) + (y0 << 7);
        const float* pl11 = lab + vol_base + (x1 << 14) + (y1 << 7);

        #pragma unroll
        for (int k = 0; k < 4; k++) {
            const float zn = zn0 + 0.5f * (float)k;          // exact
            const float zs = __fadd_rn(__fadd_rn(uz, __fmul_rn(t22, zn)), t23);
            const float Z = unnorm_clamp(zs);
            const float z0f = floorf(Z);
            const float fz = __fsub_rn(Z, z0f);
            const int z0 = (int)z0f;
            const int z1 = min(z0 + 1, 127);
            const float wz0 = __fsub_rn(1.0f, fz), wz1 = fz;

            const float m00 = __fmul_rn(wz0, wy0);
            const float m01 = __fmul_rn(wz0, wy1);
            const float m10 = __fmul_rn(wz1, wy0);
            const float m11 = __fmul_rn(wz1, wy1);
            const float wA = __fmul_rn(m00, wx0), wB = __fmul_rn(m00, wx1);
            const float wC = __fmul_rn(m01, wx0), wD = __fmul_rn(m01, wx1);
            const float wE = __fmul_rn(m10, wx0), wF = __fmul_rn(m10, wx1);
            const float wG = __fmul_rn(m11, wx0), wH = __fmul_rn(m11, wx1);

            const int idx = out_base + lane + 32 * k;

            // ---- phase 1: input volume (FMA allowed, same order) ----
            {
                const float vA = __ldg(pi00 + z0);
                const float vB = __ldg(pi10 + z0);
                const float vC = __ldg(pi01 + z0);
                const float vD = __ldg(pi11 + z0);
                const float vE = __ldg(pi00 + z1);
                const float vF = __ldg(pi10 + z1);
                const float vG = __ldg(pi01 + z1);
                const float vH = __ldg(pi11 + z1);
                float ai = 0.0f;
                ai = fmaf(vA, wA, ai);
                ai = fmaf(vB, wB, ai);
                ai = fmaf(vC, wC, ai);
                ai = fmaf(vD, wD, ai);
                ai = fmaf(vE, wE, ai);
                ai = fmaf(vF, wF, ai);
                ai = fmaf(vG, wG, ai);
                ai = fmaf(vH, wH, ai);
                out[idx] = ai;
            }
            // ---- phase 2: label volume (exact reference sequence) ----
            {
                const float vA = __ldg(pl00 + z0);
                const float vB = __ldg(pl10 + z0);
                const float vC = __ldg(pl01 + z0);
                const float vD = __ldg(pl11 + z0);
                const float vE = __ldg(pl00 + z1);
                const float vF = __ldg(pl10 + z1);
                const float vG = __ldg(pl01 + z1);
                const float vH = __ldg(pl11 + z1);
                float al = 0.0f;
                al = __fadd_rn(al, __fmul_rn(vA, wA));
                al = __fadd_rn(al, __fmul_rn(vB, wB));
                al = __fadd_rn(al, __fmul_rn(vC, wC));
                al = __fadd_rn(al, __fmul_rn(vD, wD));
                al = __fadd_rn(al, __fmul_rn(vE, wE));
                al = __fadd_rn(al, __fmul_rn(vF, wF));
                al = __fadd_rn(al, __fmul_rn(vG, wG));
                al = __fadd_rn(al, __fmul_rn(vH, wH));
                out[idx + N_VOX] = (al > 0.5f) ? 1.0f : 0.0f;
            }
        }
    } else {
        // generic exact path (not taken for this transform; kept correct,
        // unroll suppressed to limit its register footprint)
        #pragma unroll 1
        for (int k = 0; k < 4; k++) {
            const int w = lane + 32 * k;
            const float zn = (2.0f * (float)w + 1.0f) * inv128 - 1.0f;
            const float xs = __fadd_rn(__fadd_rn(ux, __fmul_rn(t02, zn)), t03);
            const float ys = __fadd_rn(__fadd_rn(uy, __fmul_rn(t12, zn)), t13);
            const float zs = __fadd_rn(__fadd_rn(uz, __fmul_rn(t22, zn)), t23);
            const float X = unnorm_clamp(xs);
            const float Y = unnorm_clamp(ys);
            const float Z = unnorm_clamp(zs);
            const float x0f = floorf(X), y0f = floorf(Y), z0f = floorf(Z);
            const float fx = __fsub_rn(X, x0f);
            const float fy = __fsub_rn(Y, y0f);
            const float fz = __fsub_rn(Z, z0f);
            const int x0 = (int)x0f, y0 = (int)y0f, z0 = (int)z0f;
            const int x1 = min(x0 + 1, 127);
            const int y1 = min(y0 + 1, 127);
            const int z1 = min(z0 + 1, 127);
            const float wx0 = __fsub_rn(1.0f, fx), wx1 = fx;
            const float wy0 = __fsub_rn(1.0f, fy), wy1 = fy;
            const float wz0 = __fsub_rn(1.0f, fz), wz1 = fz;

            const int r00 = vol_base + (x0 << 14) + (y0 << 7);
            const int r01 = vol_base + (x0 << 14) + (y1 << 7);
            const int r10 = vol_base + (x1 << 14) + (y0 << 7);
            const int r11 = vol_base + (x1 << 14) + (y1 << 7);

            const float m00 = __fmul_rn(wz0, wy0);
            const float m01 = __fmul_rn(wz0, wy1);
            const float m10 = __fmul_rn(wz1, wy0);
            const float m11 = __fmul_rn(wz1, wy1);
            const float wA = __fmul_rn(m00, wx0), wB = __fmul_rn(m00, wx1);
            const float wC = __fmul_rn(m01, wx0), wD = __fmul_rn(m01, wx1);
            const float wE = __fmul_rn(m10, wx0), wF = __fmul_rn(m10, wx1);
            const float wG = __fmul_rn(m11, wx0), wH = __fmul_rn(m11, wx1);

            float ai = 0.0f;
            ai = __fadd_rn(ai, __fmul_rn(__ldg(inp + r00 + z0), wA));
            ai = __fadd_rn(ai, __fmul_rn(__ldg(inp + r10 + z0), wB));
            ai = __fadd_rn(ai, __fmul_rn(__ldg(inp + r01 + z0), wC));
            ai = __fadd_rn(ai, __fmul_rn(__ldg(inp + r11 + z0), wD));
            ai = __fadd_rn(ai, __fmul_rn(__ldg(inp + r00 + z1), wE));
            ai = __fadd_rn(ai, __fmul_rn(__ldg(inp + r10 + z1), wF));
            ai = __fadd_rn(ai, __fmul_rn(__ldg(inp + r01 + z1), wG));
            ai = __fadd_rn(ai, __fmul_rn(__ldg(inp + r11 + z1), wH));
            out[out_base + w] = ai;

            float al = 0.0f;
            al = __fadd_rn(al, __fmul_rn(__ldg(lab + r00 + z0), wA));
            al = __fadd_rn(al, __fmul_rn(__ldg(lab + r10 + z0), wB));
            al = __fadd_rn(al, __fmul_rn(__ldg(lab + r01 + z0), wC));
            al = __fadd_rn(al, __fmul_rn(__ldg(lab + r11 + z0), wD));
            al = __fadd_rn(al, __fmul_rn(__ldg(lab + r00 + z1), wE));
            al = __fadd_rn(al, __fmul_rn(__ldg(lab + r10 + z1), wF));
            al = __fadd_rn(al, __fmul_rn(__ldg(lab + r01 + z1), wG));
            al = __fadd_rn(al, __fmul_rn(__ldg(lab + r11 + z1), wH));
            out[out_base + w + N_VOX] = (al > 0.5f) ? 1.0f : 0.0f;
        }
    }
}

extern "C" void kernel_launch(void* const* d_in, const int* in_sizes, int n_in,
                              void* d_out, int out_size)
{
    const float* inp = (const float*)d_in[0];   // input_g  [8,1,128,128,128]
    const float* lab = (const float*)d_in[1];   // label_g  [8,1,128,128,128]
    const float* T   = (const float*)d_in[2];   // transform 4x4 (16 floats)
    float* out = (float*)d_out;

    // 131072 rows, 8 rows (warps) per block
    seg_aug_kernel<<<16384, 256>>>(inp, lab, T, out);
}